// round 10
// baseline (speedup 1.0000x reference)
#include <cuda_runtime.h>
#include <cuda_bf16.h>
#include <cstdint>

#define B_   16
#define F_   256
#define T_   4096
#define L_   128
#define M_   1024
#define D_   128
#define TC_  2048
#define N_   32768

#define OFF_VF  16777216
#define OFF_IND 25165824

// device scratch
__device__ __align__(16) __nv_bfloat16 g_xh16[2][N_][D_];
__device__ __align__(16) __nv_bfloat16 g_xl16[2][N_][D_];
__device__ __align__(16) float         g_xf  [2][N_][D_];
__device__ __align__(16) __nv_bfloat16 g_eh16[2][M_][D_];
__device__ __align__(16) __nv_bfloat16 g_el16[2][M_][D_];
__device__ __align__(16) float g_cm[2][M_];
__device__ __align__(16) int   g_idx[2][N_];
__device__ __align__(16) float g_P[2][2][M_][256];   // [i][cf][m][f]
__device__ int   g_fixc;
__device__ int   g_fixn[N_ * 2];

// ---- fp32x2 helpers ----
__device__ __forceinline__ unsigned long long pkdup(float x) {
    unsigned long long r; unsigned int xi = __float_as_uint(x);
    asm("mov.b64 %0, {%1, %2};" : "=l"(r) : "r"(xi), "r"(xi));
    return r;
}
__device__ __forceinline__ void ffma2(unsigned long long &acc, unsigned long long a,
                                      unsigned long long b) {
    asm("fma.rn.f32x2 %0, %1, %2, %0;" : "+l"(acc) : "l"(a), "l"(b));
}
__device__ __forceinline__ float2 upk(unsigned long long v) {
    unsigned int lo, hi;
    asm("mov.b64 {%0, %1}, %2;" : "=r"(lo), "=r"(hi) : "l"(v));
    float2 r; r.x = __uint_as_float(lo); r.y = __uint_as_float(hi);
    return r;
}

// ---- mma helpers ----
__device__ __forceinline__ uint32_t sm_u32(const void* p) {
    uint32_t a;
    asm("{ .reg .u64 t; cvta.to.shared.u64 t, %1; cvt.u32.u64 %0, t; }" : "=r"(a) : "l"(p));
    return a;
}
__device__ __forceinline__ void ldsm4(uint32_t& r0, uint32_t& r1, uint32_t& r2, uint32_t& r3,
                                      uint32_t a) {
    asm volatile("ldmatrix.sync.aligned.m8n8.x4.shared.b16 {%0,%1,%2,%3}, [%4];"
                 : "=r"(r0), "=r"(r1), "=r"(r2), "=r"(r3) : "r"(a));
}
__device__ __forceinline__ void mma16816(float* c, uint32_t a0, uint32_t a1, uint32_t a2,
                                         uint32_t a3, uint32_t b0, uint32_t b1) {
    asm volatile(
        "mma.sync.aligned.m16n8k16.row.col.f32.bf16.bf16.f32 "
        "{%0,%1,%2,%3},{%4,%5,%6,%7},{%8,%9},{%0,%1,%2,%3};"
        : "+f"(c[0]), "+f"(c[1]), "+f"(c[2]), "+f"(c[3])
        : "r"(a0), "r"(a1), "r"(a2), "r"(a3), "r"(b0), "r"(b1));
}

// ---------- k_prep: codebook bf16 hi/lo split + cm ----------
__global__ void k_prep(const float* __restrict__ cb) {
    if (blockIdx.x == 0 && blockIdx.y == 0 && threadIdx.x == 0) g_fixc = 0;
    int w = threadIdx.x >> 5, lane = threadIdx.x & 31;
    int i = blockIdx.y, m = blockIdx.x * 8 + w;
    const float* row = cb + (size_t)(i * M_ + m) * D_;
    float4 v = *(const float4*)(row + lane * 4);
    float s = v.x * v.x + v.y * v.y + v.z * v.z + v.w * v.w;
    float vv[4] = {v.x, v.y, v.z, v.w};
#pragma unroll
    for (int j = 0; j < 4; j++) {
        __nv_bfloat16 hb = __float2bfloat16(vv[j]);
        g_eh16[i][m][lane * 4 + j] = hb;
        g_el16[i][m][lane * 4 + j] = __float2bfloat16(vv[j] - __bfloat162float(hb));
    }
#pragma unroll
    for (int o = 16; o >= 1; o >>= 1) s += __shfl_xor_sync(0xffffffffu, s, o);
    if (lane == 0) g_cm[i][m] = -5.0f * s;
}

// ---------- k_prep2: P[i][cf][m][f] = sum_j e_i[m][cf*64+j] * w2[f][i*64+j] ----------
__global__ void k_prep2(const float* __restrict__ cb, const float* __restrict__ w2) {
    __shared__ float es[32][64];
    int tid = threadIdx.x;
    int m0 = blockIdx.x << 5, cf = blockIdx.y, i = blockIdx.z;
#pragma unroll
    for (int k = 0; k < 2; k++) {
        int u = tid + (k << 8);
        int m = u >> 4, d4 = u & 15;
        *(float4*)&es[m][d4 << 2] =
            *(const float4*)(cb + (size_t)(i * M_ + m0 + m) * D_ + cf * 64 + (d4 << 2));
    }
    __syncthreads();
    int f = tid;
    float4 wr[16];
    const float4* wp = (const float4*)(w2 + f * D_ + i * 64);
#pragma unroll
    for (int j = 0; j < 16; j++) wr[j] = wp[j];
#pragma unroll 4
    for (int m = 0; m < 32; m++) {
        float s = 0.f;
        const float4* ep = (const float4*)&es[m][0];
#pragma unroll
        for (int j = 0; j < 16; j++) {
            float4 e = ep[j], w = wr[j];
            s += e.x * w.x + e.y * w.y + e.z * w.z + e.w * w.w;
        }
        g_P[i][cf][m0 + m][f] = s;
    }
}

// ---------- k_conv1: conv1x1_1 + bf16 split ----------
__global__ void __launch_bounds__(256, 2) k_conv1(const float* __restrict__ in,
                                                  const float* __restrict__ w1) {
    __shared__ float sm[2 * 32 * 136];
    float* Aw = sm;
    float* Bi = sm + 32 * 136;
    int tid = threadIdx.x, tx = tid & 15, ty = tid >> 4;
    int b = blockIdx.y, t0 = blockIdx.x << 7;

    unsigned long long acc[8][4];
#pragma unroll
    for (int a = 0; a < 8; a++)
#pragma unroll
        for (int q = 0; q < 4; q++) acc[a][q] = 0ULL;

    for (int kc = 0; kc < 8; kc++) {
        int f0 = kc << 5;
#pragma unroll
        for (int r = 0; r < 4; r++) {
            int lin = tid + (r << 8);
            int l = lin >> 3, fq = (lin & 7) << 2;
            float4 v = *(const float4*)(w1 + l * F_ + f0 + fq);
            Aw[(fq + 0) * 136 + l] = v.x; Aw[(fq + 1) * 136 + l] = v.y;
            Aw[(fq + 2) * 136 + l] = v.z; Aw[(fq + 3) * 136 + l] = v.w;
        }
#pragma unroll
        for (int r = 0; r < 4; r++) {
            int lin = tid + (r << 8);
            int f = lin >> 5, tq = (lin & 31) << 2;
            float4 v = *(const float4*)(in + (size_t)(b * F_ + f0 + f) * T_ + t0 + tq);
            *(float4*)(Bi + f * 136 + tq) = v;
        }
        __syncthreads();
#pragma unroll 8
        for (int f = 0; f < 32; f++) {
            float4 a0 = *(const float4*)(Aw + f * 136 + ty * 8);
            float4 a1 = *(const float4*)(Aw + f * 136 + ty * 8 + 4);
            const unsigned long long* bp = (const unsigned long long*)(Bi + f * 136 + tx * 8);
            unsigned long long b0 = bp[0], b1 = bp[1], b2 = bp[2], b3 = bp[3];
            unsigned long long ad[8] = {pkdup(a0.x), pkdup(a0.y), pkdup(a0.z), pkdup(a0.w),
                                        pkdup(a1.x), pkdup(a1.y), pkdup(a1.z), pkdup(a1.w)};
#pragma unroll
            for (int a = 0; a < 8; a++) {
                ffma2(acc[a][0], ad[a], b0);
                ffma2(acc[a][1], ad[a], b1);
                ffma2(acc[a][2], ad[a], b2);
                ffma2(acc[a][3], ad[a], b3);
            }
        }
        __syncthreads();
    }

    int nb = b * TC_ + (t0 >> 1);
    for (int h = 0; h < 2; h++) {
        if ((tx >> 3) == h) {
#pragma unroll
            for (int a = 0; a < 8; a++)
#pragma unroll
                for (int q = 0; q < 4; q++) {
                    float2 s = upk(acc[a][q]);
                    int tl = ((tx & 7) << 3) + (q << 1);
                    sm[tl * 129 + ty * 8 + a] = s.x;
                    sm[(tl + 1) * 129 + ty * 8 + a] = s.y;
                }
        }
        __syncthreads();
#pragma unroll
        for (int w = 0; w < 32; w++) {
            int e = (w << 8) + tid;
            int d = e & 127, cbb = (e >> 7) & 1, nn = e >> 8;
            float v = sm[(2 * nn + (d >> 6)) * 129 + (cbb << 6) + (d & 63)];
            int n = nb + h * 32 + nn;
            __nv_bfloat16 hb = __float2bfloat16(v);
            g_xh16[cbb][n][d] = hb;
            g_xl16[cbb][n][d] = __float2bfloat16(v - __bfloat162float(hb));
            g_xf[cbb][n][d] = v;
        }
        __syncthreads();
    }
}

// ---------- k_dist_mma v5: 64-row tiles, 2 CTAs/SM ----------
// smem: Xh@0 (16K), Xl@16384, E@32768 (32K), cms@65536 (4K), red@69632
#define DSM_TOT 70656

__device__ __forceinline__ void do_pass64(uint32_t sX, uint32_t sE, int lane, int wr, int wc,
                                          float c[8][4]) {
#pragma unroll
    for (int ks = 0; ks < 8; ks++) {
        uint32_t a0, a1, a2, a3;
        int rowA = wr * 16 + (lane & 15);
        int koA = ks * 2 + (lane >> 4);
        ldsm4(a0, a1, a2, a3, sX + rowA * 256 + ((koA ^ (rowA & 7)) << 4));
#pragma unroll
        for (int pr = 0; pr < 4; pr++) {
            int nB = wc * 64 + pr * 16 + (lane & 7) + ((lane >> 4) << 3);
            int koB = ks * 2 + ((lane >> 3) & 1);
            uint32_t b0, b1, b2, b3;
            ldsm4(b0, b1, b2, b3, sE + nB * 256 + ((koB ^ (nB & 7)) << 4));
            mma16816(c[pr * 2],     a0, a1, a2, a3, b0, b1);
            mma16816(c[pr * 2 + 1], a0, a1, a2, a3, b2, b3);
        }
    }
}

__global__ void __launch_bounds__(256, 2) k_dist_mma(const float* __restrict__ gum) {
    extern __shared__ char smem[];
    float* cms = (float*)(smem + 65536);
    float* redv = (float*)(smem + 69632);
    float* redb = redv + 64;
    int*   redi = (int*)(redb + 64);
    uint32_t sXh = sm_u32(smem), sXl = sXh + 16384, sE = sXh + 32768;

    int tid = threadIdx.x, lane = tid & 31, wid = tid >> 5;
    int wr = wid >> 1, wc = wid & 1;
    int cbi = blockIdx.y, n0 = blockIdx.x << 6;

    // stage X (64 rows, both planes, swizzled) + cms
#pragma unroll
    for (int i = 0; i < 4; i++) {
        int lin = tid + (i << 8);
        int row = lin >> 4, ko = lin & 15;
        uint32_t off = row * 256 + ((ko ^ (row & 7)) << 4);
        *(uint4*)(smem + off)         = *(const uint4*)(&g_xh16[cbi][n0 + row][ko * 8]);
        *(uint4*)(smem + 16384 + off) = *(const uint4*)(&g_xl16[cbi][n0 + row][ko * 8]);
    }
    *(float4*)(&cms[tid * 4]) = *(const float4*)(&g_cm[cbi][tid * 4]);

    float best[2], b2[2]; int bm[2];
#pragma unroll
    for (int s = 0; s < 2; s++) { best[s] = -3.4e38f; b2[s] = -3.4e38f; bm[s] = 0; }

#pragma unroll 1
    for (int mc = 0; mc < 8; mc++) {
        float c[8][4];
#pragma unroll
        for (int tn = 0; tn < 8; tn++)
#pragma unroll
            for (int q = 0; q < 4; q++) c[tn][q] = 0.f;

        const __nv_bfloat16* ehp = &g_eh16[cbi][mc << 7][0];
        const __nv_bfloat16* elp = &g_el16[cbi][mc << 7][0];

        __syncthreads();
#pragma unroll
        for (int i = 0; i < 8; i++) {
            int lin = tid + (i << 8);
            int row = lin >> 4, ko = lin & 15;
            *(uint4*)(smem + 32768 + row * 256 + ((ko ^ (row & 7)) << 4)) =
                *(const uint4*)(ehp + row * 128 + ko * 8);
        }
        __syncthreads();
        do_pass64(sXh, sE, lane, wr, wc, c);   // Xh * Eh
        do_pass64(sXl, sE, lane, wr, wc, c);   // Xl * Eh
        __syncthreads();
#pragma unroll
        for (int i = 0; i < 8; i++) {
            int lin = tid + (i << 8);
            int row = lin >> 4, ko = lin & 15;
            *(uint4*)(smem + 32768 + row * 256 + ((ko ^ (row & 7)) << 4)) =
                *(const uint4*)(elp + row * 128 + ko * 8);
        }
        __syncthreads();
        do_pass64(sXh, sE, lane, wr, wc, c);   // Xh * El

        // epilogue: +cm +gumbel, running top-2 argmax
        int colbase = (mc << 7) + wc * 64 + ((lane & 3) << 1);
        int r0 = n0 + wr * 16 + (lane >> 2);
        const float* gr0 = gum + ((size_t)cbi * N_ + r0) * (size_t)M_;
        const float* gr1 = gr0 + (size_t)8 * M_;
#pragma unroll
        for (int tn = 0; tn < 8; tn++) {
            int col = colbase + tn * 8;
            float cm0 = cms[col], cm1 = cms[col + 1];
            float2 ga = *(const float2*)(gr0 + col);
            float2 gb = *(const float2*)(gr1 + col);
            float* cc = c[tn];
            float v0 = fmaf(10.f, cc[0], cm0 + ga.x);
            float v1 = fmaf(10.f, cc[1], cm1 + ga.y);
            float v2 = fmaf(10.f, cc[2], cm0 + gb.x);
            float v3 = fmaf(10.f, cc[3], cm1 + gb.y);
            if (v0 > best[0]) { b2[0] = best[0]; best[0] = v0; bm[0] = col; }
            else if (v0 > b2[0]) b2[0] = v0;
            if (v1 > best[0]) { b2[0] = best[0]; best[0] = v1; bm[0] = col + 1; }
            else if (v1 > b2[0]) b2[0] = v1;
            if (v2 > best[1]) { b2[1] = best[1]; best[1] = v2; bm[1] = col; }
            else if (v2 > b2[1]) b2[1] = v2;
            if (v3 > best[1]) { b2[1] = best[1]; best[1] = v3; bm[1] = col + 1; }
            else if (v3 > b2[1]) b2[1] = v3;
        }
    }

    // quad reduce (lanes sharing the same rows: lane&3)
#pragma unroll
    for (int s = 0; s < 2; s++) {
#pragma unroll
        for (int off = 1; off <= 2; off <<= 1) {
            float ov = __shfl_xor_sync(0xffffffffu, best[s], off);
            float o2 = __shfl_xor_sync(0xffffffffu, b2[s], off);
            int om = __shfl_xor_sync(0xffffffffu, bm[s], off);
            if (ov > best[s]) { b2[s] = fmaxf(best[s], o2); best[s] = ov; bm[s] = om; }
            else if (ov == best[s]) { b2[s] = best[s]; if (om < bm[s]) bm[s] = om; }
            else b2[s] = fmaxf(b2[s], fmaxf(ov, o2));
        }
    }
    __syncthreads();
    if (wc == 0 && (lane & 3) == 0) {
#pragma unroll
        for (int s = 0; s < 2; s++) {
            int lr = wr * 16 + (s << 3) + (lane >> 2);
            redv[lr] = best[s]; redb[lr] = b2[s]; redi[lr] = bm[s];
        }
    }
    __syncthreads();
    if (wc == 1 && (lane & 3) == 0) {
#pragma unroll
        for (int s = 0; s < 2; s++) {
            int lr = wr * 16 + (s << 3) + (lane >> 2);
            float ov = redv[lr], o2 = redb[lr]; int om = redi[lr];
            if (ov > best[s]) { b2[s] = fmaxf(best[s], o2); best[s] = ov; bm[s] = om; }
            else if (ov == best[s]) { b2[s] = best[s]; if (om < bm[s]) bm[s] = om; }
            else b2[s] = fmaxf(b2[s], fmaxf(ov, o2));
            int n = n0 + lr;
            g_idx[cbi][n] = bm[s];
            if (best[s] - b2[s] < 2e-2f) {
                int k = atomicAdd(&g_fixc, 1);
                g_fixn[k] = (cbi << 15) | n;
            }
        }
    }
}

// ---------- k_fix v2: exact fp32 rescore, float4 + 4-way ILP ----------
__global__ void k_fix(const float* __restrict__ cb, const float* __restrict__ gum) {
    __shared__ float4 xs4[32];
    __shared__ float rv[256];
    __shared__ int ri[256];
    int nfix = g_fixc;
    int tid = threadIdx.x;
    for (int it = blockIdx.x; it < nfix; it += gridDim.x) {
        int row = g_fixn[it];
        int cbi = row >> 15, n = row & 32767;
        if (tid < 32) xs4[tid] = *(const float4*)(&g_xf[cbi][n][tid * 4]);
        __syncthreads();
        const float4* e0 = (const float4*)(cb + (size_t)(cbi * M_ + tid) * D_);
        const float4* e1 = e0 + 256 * 32;
        const float4* e2 = e0 + 512 * 32;
        const float4* e3 = e0 + 768 * 32;
        float s0 = 0.f, s1 = 0.f, s2 = 0.f, s3 = 0.f;
#pragma unroll
        for (int d4 = 0; d4 < 32; d4++) {
            float4 x = xs4[d4];
            float4 a = e0[d4], b = e1[d4], cc = e2[d4], d = e3[d4];
            s0 += a.x * x.x + a.y * x.y + a.z * x.z + a.w * x.w;
            s1 += b.x * x.x + b.y * x.y + b.z * x.z + b.w * x.w;
            s2 += cc.x * x.x + cc.y * x.y + cc.z * x.z + cc.w * x.w;
            s3 += d.x * x.x + d.y * x.y + d.z * x.z + d.w * x.w;
        }
        const float* gr = gum + ((size_t)cbi * N_ + n) * (size_t)M_;
        float sc0 = 10.f * s0 + g_cm[cbi][tid]       + gr[tid];
        float sc1 = 10.f * s1 + g_cm[cbi][tid + 256] + gr[tid + 256];
        float sc2 = 10.f * s2 + g_cm[cbi][tid + 512] + gr[tid + 512];
        float sc3 = 10.f * s3 + g_cm[cbi][tid + 768] + gr[tid + 768];
        float best = sc0; int bmv = tid;
        if (sc1 > best) { best = sc1; bmv = tid + 256; }
        if (sc2 > best) { best = sc2; bmv = tid + 512; }
        if (sc3 > best) { best = sc3; bmv = tid + 768; }
        rv[tid] = best; ri[tid] = bmv;
        __syncthreads();
        for (int st = 128; st >= 1; st >>= 1) {
            if (tid < st) {
                if (rv[tid + st] > rv[tid] ||
                    (rv[tid + st] == rv[tid] && ri[tid + st] < ri[tid])) {
                    rv[tid] = rv[tid + st]; ri[tid] = ri[tid + st];
                }
            }
            __syncthreads();
        }
        if (tid == 0) g_idx[cbi][n] = ri[0];
        __syncthreads();
    }
}

// ---------- k_gather: vq_feat + inds outputs ----------
__global__ void k_gather(const float* __restrict__ cb, float* __restrict__ dout,
                         int write_vf, int write_inds) {
    int gt = blockIdx.x * 256 + threadIdx.x;
    int l4 = gt & 31;
    int t = (gt >> 5) & 4095;
    int b = gt >> 17;
    int l = l4 << 2;
    int ci = l >> 6;
    int cf = t & 1;
    int n = b * TC_ + (t >> 1);
    if (write_vf) {
        int idx = g_idx[ci][n];
        float4 v = *(const float4*)(cb + (size_t)(ci * M_ + idx) * D_ + (cf << 6) + (l & 63));
        *(float4*)(dout + OFF_VF + ((size_t)gt << 2)) = v;
    }
    if (write_inds && gt < 65536) {
        int ii = gt & 1, nn = gt >> 1;
        dout[OFF_IND + gt] = (float)g_idx[ii][nn];
    }
}

// ---------- k_out: out[b][f][t] = P[0][cf][idx0][f] + P[1][cf][idx1][f] ----------
__global__ void k_out(float* __restrict__ dout) {
    __shared__ float sm[32 * 256];
    __shared__ int idxs[64];
    int tid = threadIdx.x;
    int b = blockIdx.x >> 7;
    int t0 = (blockIdx.x & 127) << 5;
    if (tid < 32) {
        int n = b * TC_ + ((t0 + tid) >> 1);
        idxs[tid] = g_idx[0][n];
        idxs[32 + tid] = g_idx[1][n];
    }
    __syncthreads();
    float4* sm4 = (float4*)sm;
#pragma unroll
    for (int k = 0; k < 8; k++) {
        int u = tid + (k << 8);
        int tl = u >> 6, f4 = u & 63;
        int cf = tl & 1;
        const float4* p0 = (const float4*)&g_P[0][cf][idxs[tl]][f4 << 2];
        const float4* p1 = (const float4*)&g_P[1][cf][idxs[32 + tl]][f4 << 2];
        float4 a = *p0, bb = *p1;
        float4 v = make_float4(a.x + bb.x, a.y + bb.y, a.z + bb.z, a.w + bb.w);
        sm4[tl * 64 + (f4 ^ tl)] = v;
    }
    __syncthreads();
    int w = tid >> 5, lane = tid & 31;
#pragma unroll
    for (int j = 0; j < 32; j++) {
        int f = w * 32 + j;
        int cswz = ((f >> 2) ^ lane) & 63;
        float v = sm[lane * 256 + (cswz << 2) + (f & 3)];
        dout[(size_t)(b * F_ + f) * T_ + t0 + lane] = v;
    }
}

extern "C" void kernel_launch(void* const* d_in, const int* in_sizes, int n_in,
                              void* d_out, int out_size) {
    const float* in  = (const float*)d_in[0];
    const float* w1  = (const float*)d_in[1];
    const float* w2  = (const float*)d_in[2];
    const float* cb  = (const float*)d_in[3];
    const float* gum = (const float*)d_in[4];
    float* dout = (float*)d_out;

    int write_vf   = (out_size >= OFF_VF + B_ * T_ * L_) ? 1 : 0;
    int write_inds = (out_size >= OFF_IND + N_ * 2) ? 1 : 0;

    cudaFuncSetAttribute(k_dist_mma, cudaFuncAttributeMaxDynamicSharedMemorySize, DSM_TOT);

    k_prep2<<<dim3(32, 2, 2), 256>>>(cb, w2);
    k_prep<<<dim3(128, 2), 256>>>(cb);
    k_conv1<<<dim3(32, 16), 256>>>(in, w1);
    k_dist_mma<<<dim3(512, 2), 256, DSM_TOT>>>(gum);
    k_fix<<<256, 256>>>(cb, gum);
    k_gather<<<8192, 256>>>(cb, dout, write_vf, write_inds);
    k_out<<<2048, 256>>>(dout);
}

// round 11
// speedup vs baseline: 1.0960x; 1.0960x over previous
#include <cuda_runtime.h>
#include <cuda_bf16.h>
#include <cstdint>

#define B_   16
#define F_   256
#define T_   4096
#define L_   128
#define M_   1024
#define D_   128
#define TC_  2048
#define N_   32768

#define OFF_VF  16777216
#define OFF_IND 25165824

// device scratch
__device__ __align__(16) __nv_bfloat16 g_xh16[2][N_][D_];
__device__ __align__(16) __nv_bfloat16 g_xl16[2][N_][D_];
__device__ __align__(16) float         g_xf  [2][N_][D_];
__device__ __align__(16) __nv_bfloat16 g_eh16[2][M_][D_];
__device__ __align__(16) __nv_bfloat16 g_el16[2][M_][D_];
__device__ __align__(16) float g_cm[2][M_];
__device__ __align__(16) int   g_idx[2][N_];
__device__ __align__(16) float g_P[2][2][M_][256];   // [i][cf][m][f]
__device__ int   g_fixc;
__device__ int   g_fixn[N_ * 2];

// ---- fp32x2 helpers ----
__device__ __forceinline__ unsigned long long pkdup(float x) {
    unsigned long long r; unsigned int xi = __float_as_uint(x);
    asm("mov.b64 %0, {%1, %2};" : "=l"(r) : "r"(xi), "r"(xi));
    return r;
}
__device__ __forceinline__ void ffma2(unsigned long long &acc, unsigned long long a,
                                      unsigned long long b) {
    asm("fma.rn.f32x2 %0, %1, %2, %0;" : "+l"(acc) : "l"(a), "l"(b));
}
__device__ __forceinline__ float2 upk(unsigned long long v) {
    unsigned int lo, hi;
    asm("mov.b64 {%0, %1}, %2;" : "=r"(lo), "=r"(hi) : "l"(v));
    float2 r; r.x = __uint_as_float(lo); r.y = __uint_as_float(hi);
    return r;
}

// ---- mma / bulk-async helpers ----
__device__ __forceinline__ uint32_t sm_u32(const void* p) {
    uint32_t a;
    asm("{ .reg .u64 t; cvta.to.shared.u64 t, %1; cvt.u32.u64 %0, t; }" : "=r"(a) : "l"(p));
    return a;
}
__device__ __forceinline__ void ldsm4(uint32_t& r0, uint32_t& r1, uint32_t& r2, uint32_t& r3,
                                      uint32_t a) {
    asm volatile("ldmatrix.sync.aligned.m8n8.x4.shared.b16 {%0,%1,%2,%3}, [%4];"
                 : "=r"(r0), "=r"(r1), "=r"(r2), "=r"(r3) : "r"(a));
}
__device__ __forceinline__ void mma16816(float* c, uint32_t a0, uint32_t a1, uint32_t a2,
                                         uint32_t a3, uint32_t b0, uint32_t b1) {
    asm volatile(
        "mma.sync.aligned.m16n8k16.row.col.f32.bf16.bf16.f32 "
        "{%0,%1,%2,%3},{%4,%5,%6,%7},{%8,%9},{%0,%1,%2,%3};"
        : "+f"(c[0]), "+f"(c[1]), "+f"(c[2]), "+f"(c[3])
        : "r"(a0), "r"(a1), "r"(a2), "r"(a3), "r"(b0), "r"(b1));
}
__device__ __forceinline__ void mb_init(uint32_t a, uint32_t cnt) {
    asm volatile("mbarrier.init.shared.b64 [%0], %1;" :: "r"(a), "r"(cnt) : "memory");
}
__device__ __forceinline__ void mb_expect_tx(uint32_t a, uint32_t bytes) {
    asm volatile("mbarrier.arrive.expect_tx.shared.b64 _, [%0], %1;"
                 :: "r"(a), "r"(bytes) : "memory");
}
__device__ __forceinline__ void bulk_cp(uint32_t dst, const void* src, uint32_t bytes,
                                        uint32_t mbar) {
    asm volatile(
        "cp.async.bulk.shared::cta.global.mbarrier::complete_tx::bytes [%0], [%1], %2, [%3];"
        :: "r"(dst), "l"(src), "r"(bytes), "r"(mbar) : "memory");
}
__device__ __forceinline__ void mb_wait(uint32_t mbar, uint32_t parity) {
    asm volatile(
        "{\n\t.reg .pred P;\n\t"
        "W_%=:\n\t"
        "mbarrier.try_wait.parity.acquire.cta.shared::cta.b64 P, [%0], %1, 0x989680;\n\t"
        "@P bra.uni D_%=;\n\t"
        "bra.uni W_%=;\n\t"
        "D_%=:\n\t}"
        :: "r"(mbar), "r"(parity) : "memory");
}

// ---------- k_prep: codebook bf16 hi/lo split + cm ----------
__global__ void k_prep(const float* __restrict__ cb) {
    if (blockIdx.x == 0 && blockIdx.y == 0 && threadIdx.x == 0) g_fixc = 0;
    int w = threadIdx.x >> 5, lane = threadIdx.x & 31;
    int i = blockIdx.y, m = blockIdx.x * 8 + w;
    const float* row = cb + (size_t)(i * M_ + m) * D_;
    float4 v = *(const float4*)(row + lane * 4);
    float s = v.x * v.x + v.y * v.y + v.z * v.z + v.w * v.w;
    float vv[4] = {v.x, v.y, v.z, v.w};
#pragma unroll
    for (int j = 0; j < 4; j++) {
        __nv_bfloat16 hb = __float2bfloat16(vv[j]);
        g_eh16[i][m][lane * 4 + j] = hb;
        g_el16[i][m][lane * 4 + j] = __float2bfloat16(vv[j] - __bfloat162float(hb));
    }
#pragma unroll
    for (int o = 16; o >= 1; o >>= 1) s += __shfl_xor_sync(0xffffffffu, s, o);
    if (lane == 0) g_cm[i][m] = -5.0f * s;
}

// ---------- k_prep2: P[i][cf][m][f] = sum_j e_i[m][cf*64+j] * w2[f][i*64+j] ----------
__global__ void k_prep2(const float* __restrict__ cb, const float* __restrict__ w2) {
    __shared__ float es[32][64];
    int tid = threadIdx.x;
    int m0 = blockIdx.x << 5, cf = blockIdx.y, i = blockIdx.z;
#pragma unroll
    for (int k = 0; k < 2; k++) {
        int u = tid + (k << 8);
        int m = u >> 4, d4 = u & 15;
        *(float4*)&es[m][d4 << 2] =
            *(const float4*)(cb + (size_t)(i * M_ + m0 + m) * D_ + cf * 64 + (d4 << 2));
    }
    __syncthreads();
    int f = tid;
    float4 wr[16];
    const float4* wp = (const float4*)(w2 + f * D_ + i * 64);
#pragma unroll
    for (int j = 0; j < 16; j++) wr[j] = wp[j];
#pragma unroll 4
    for (int m = 0; m < 32; m++) {
        float s = 0.f;
        const float4* ep = (const float4*)&es[m][0];
#pragma unroll
        for (int j = 0; j < 16; j++) {
            float4 e = ep[j], w = wr[j];
            s += e.x * w.x + e.y * w.y + e.z * w.z + e.w * w.w;
        }
        g_P[i][cf][m0 + m][f] = s;
    }
}

// ---------- k_conv1: conv1x1_1 + bf16 split ----------
__global__ void __launch_bounds__(256, 2) k_conv1(const float* __restrict__ in,
                                                  const float* __restrict__ w1) {
    __shared__ float sm[2 * 32 * 136];
    float* Aw = sm;
    float* Bi = sm + 32 * 136;
    int tid = threadIdx.x, tx = tid & 15, ty = tid >> 4;
    int b = blockIdx.y, t0 = blockIdx.x << 7;

    unsigned long long acc[8][4];
#pragma unroll
    for (int a = 0; a < 8; a++)
#pragma unroll
        for (int q = 0; q < 4; q++) acc[a][q] = 0ULL;

    for (int kc = 0; kc < 8; kc++) {
        int f0 = kc << 5;
#pragma unroll
        for (int r = 0; r < 4; r++) {
            int lin = tid + (r << 8);
            int l = lin >> 3, fq = (lin & 7) << 2;
            float4 v = *(const float4*)(w1 + l * F_ + f0 + fq);
            Aw[(fq + 0) * 136 + l] = v.x; Aw[(fq + 1) * 136 + l] = v.y;
            Aw[(fq + 2) * 136 + l] = v.z; Aw[(fq + 3) * 136 + l] = v.w;
        }
#pragma unroll
        for (int r = 0; r < 4; r++) {
            int lin = tid + (r << 8);
            int f = lin >> 5, tq = (lin & 31) << 2;
            float4 v = *(const float4*)(in + (size_t)(b * F_ + f0 + f) * T_ + t0 + tq);
            *(float4*)(Bi + f * 136 + tq) = v;
        }
        __syncthreads();
#pragma unroll 8
        for (int f = 0; f < 32; f++) {
            float4 a0 = *(const float4*)(Aw + f * 136 + ty * 8);
            float4 a1 = *(const float4*)(Aw + f * 136 + ty * 8 + 4);
            const unsigned long long* bp = (const unsigned long long*)(Bi + f * 136 + tx * 8);
            unsigned long long b0 = bp[0], b1 = bp[1], b2 = bp[2], b3 = bp[3];
            unsigned long long ad[8] = {pkdup(a0.x), pkdup(a0.y), pkdup(a0.z), pkdup(a0.w),
                                        pkdup(a1.x), pkdup(a1.y), pkdup(a1.z), pkdup(a1.w)};
#pragma unroll
            for (int a = 0; a < 8; a++) {
                ffma2(acc[a][0], ad[a], b0);
                ffma2(acc[a][1], ad[a], b1);
                ffma2(acc[a][2], ad[a], b2);
                ffma2(acc[a][3], ad[a], b3);
            }
        }
        __syncthreads();
    }

    int nb = b * TC_ + (t0 >> 1);
    for (int h = 0; h < 2; h++) {
        if ((tx >> 3) == h) {
#pragma unroll
            for (int a = 0; a < 8; a++)
#pragma unroll
                for (int q = 0; q < 4; q++) {
                    float2 s = upk(acc[a][q]);
                    int tl = ((tx & 7) << 3) + (q << 1);
                    sm[tl * 129 + ty * 8 + a] = s.x;
                    sm[(tl + 1) * 129 + ty * 8 + a] = s.y;
                }
        }
        __syncthreads();
#pragma unroll
        for (int w = 0; w < 32; w++) {
            int e = (w << 8) + tid;
            int d = e & 127, cbb = (e >> 7) & 1, nn = e >> 8;
            float v = sm[(2 * nn + (d >> 6)) * 129 + (cbb << 6) + (d & 63)];
            int n = nb + h * 32 + nn;
            __nv_bfloat16 hb = __float2bfloat16(v);
            g_xh16[cbb][n][d] = hb;
            g_xl16[cbb][n][d] = __float2bfloat16(v - __bfloat162float(hb));
            g_xf[cbb][n][d] = v;
        }
        __syncthreads();
    }
}

// ---------- k_dist_mma v6: R7 core + cp.async.bulk gumbel DMA ----------
// smem: Xh@0 Xl@32768 E@65536(32K) cms@98304(4K) G@102400(128x528B=67584)
//       red@169984 (1536B) mbar@171520
#define DSM_CMS  98304
#define DSM_G    102400
#define DSM_RED  169984
#define DSM_MBAR 171520
#define DSM_TOT  171552
#define GROW     132          // floats per gumbel smem row (528B, 16B-aligned)

__device__ __forceinline__ void do_pass(uint32_t sX, uint32_t sE, int lane, int wr, int wc,
                                        float c[2][8][4]) {
#pragma unroll
    for (int ks = 0; ks < 8; ks++) {
        uint32_t a[2][4];
#pragma unroll
        for (int tm = 0; tm < 2; tm++) {
            int rowA = wr * 32 + tm * 16 + (lane & 15);
            int koA = ks * 2 + (lane >> 4);
            ldsm4(a[tm][0], a[tm][1], a[tm][2], a[tm][3],
                  sX + rowA * 256 + ((koA ^ (rowA & 7)) << 4));
        }
#pragma unroll
        for (int pr = 0; pr < 4; pr++) {
            int nB = wc * 64 + pr * 16 + (lane & 7) + ((lane >> 4) << 3);
            int koB = ks * 2 + ((lane >> 3) & 1);
            uint32_t b0, b1, b2, b3;
            ldsm4(b0, b1, b2, b3, sE + nB * 256 + ((koB ^ (nB & 7)) << 4));
            mma16816(c[0][pr * 2],     a[0][0], a[0][1], a[0][2], a[0][3], b0, b1);
            mma16816(c[0][pr * 2 + 1], a[0][0], a[0][1], a[0][2], a[0][3], b2, b3);
            mma16816(c[1][pr * 2],     a[1][0], a[1][1], a[1][2], a[1][3], b0, b1);
            mma16816(c[1][pr * 2 + 1], a[1][0], a[1][1], a[1][2], a[1][3], b2, b3);
        }
    }
}

__global__ void __launch_bounds__(256, 1) k_dist_mma(const float* __restrict__ gum) {
    extern __shared__ char smem[];
    float* cms = (float*)(smem + DSM_CMS);
    float* gsm = (float*)(smem + DSM_G);
    float* redv = (float*)(smem + DSM_RED);
    float* redb = redv + 128;
    int*   redi = (int*)(redb + 128);
    uint32_t sXh = sm_u32(smem), sXl = sXh + 32768, sE = sXh + 65536;
    uint32_t sG = sXh + DSM_G, mbar = sXh + DSM_MBAR;

    int tid = threadIdx.x, lane = tid & 31, wid = tid >> 5;
    int wr = wid >> 1, wc = wid & 1;
    int cbi = blockIdx.y, n0 = blockIdx.x << 7;

    if (tid == 0) mb_init(mbar, 1);
    asm volatile("fence.proxy.async.shared::cta;" ::: "memory");

#pragma unroll
    for (int i = 0; i < 8; i++) {
        int lin = tid + (i << 8);
        int row = lin >> 4, ko = lin & 15;
        uint32_t off = row * 256 + ((ko ^ (row & 7)) << 4);
        *(uint4*)(smem + off)         = *(const uint4*)(&g_xh16[cbi][n0 + row][ko * 8]);
        *(uint4*)(smem + 32768 + off) = *(const uint4*)(&g_xl16[cbi][n0 + row][ko * 8]);
    }
    *(float4*)(&cms[tid * 4]) = *(const float4*)(&g_cm[cbi][tid * 4]);

    float best[4], b2[4]; int bm[4];
#pragma unroll
    for (int s = 0; s < 4; s++) { best[s] = -3.4e38f; b2[s] = -3.4e38f; bm[s] = 0; }

    const __nv_bfloat16* ehb = &g_eh16[cbi][0][0];
    const __nv_bfloat16* elb = &g_el16[cbi][0][0];
    const float* gb0 = gum + ((size_t)cbi * N_ + n0) * (size_t)M_;

#pragma unroll 1
    for (int mc = 0; mc < 8; mc++) {
        __syncthreads();   // prior epilogue done -> gsm reusable, E restageable
        // tid0 kicks the DMA engine: 128 rows x 512B of this chunk's gumbel tile
        if (tid == 0) {
            mb_expect_tx(mbar, 65536);
            const float* gsrc = gb0 + (mc << 7);
#pragma unroll 4
            for (int r = 0; r < 128; r++)
                bulk_cp(sG + r * (GROW * 4), gsrc + (size_t)r * M_, 512, mbar);
        }
        // stage Eh
#pragma unroll
        for (int i = 0; i < 8; i++) {
            int lin = tid + (i << 8);
            int row = lin >> 4, ko = lin & 15;
            *(uint4*)(smem + 65536 + row * 256 + ((ko ^ (row & 7)) << 4)) =
                *(const uint4*)(ehb + (size_t)((mc << 7) + row) * D_ + ko * 8);
        }
        __syncthreads();

        float c[2][8][4];
#pragma unroll
        for (int tm = 0; tm < 2; tm++)
#pragma unroll
            for (int tn = 0; tn < 8; tn++)
#pragma unroll
                for (int q = 0; q < 4; q++) c[tm][tn][q] = 0.f;

        do_pass(sXh, sE, lane, wr, wc, c);   // Xh * Eh
        do_pass(sXl, sE, lane, wr, wc, c);   // Xl * Eh
        __syncthreads();
        // stage El
#pragma unroll
        for (int i = 0; i < 8; i++) {
            int lin = tid + (i << 8);
            int row = lin >> 4, ko = lin & 15;
            *(uint4*)(smem + 65536 + row * 256 + ((ko ^ (row & 7)) << 4)) =
                *(const uint4*)(elb + (size_t)((mc << 7) + row) * D_ + ko * 8);
        }
        __syncthreads();
        do_pass(sXh, sE, lane, wr, wc, c);   // Xh * El

        mb_wait(mbar, mc & 1);               // gumbel tile arrived (DMA ran under passes)

        int colbase = (mc << 7) + wc * 64 + ((lane & 3) << 1);
#pragma unroll
        for (int tm = 0; tm < 2; tm++) {
            int lr = wr * 32 + tm * 16 + (lane >> 2);
            const float* gr0 = gsm + lr * GROW;
            const float* gr1 = gsm + (lr + 8) * GROW;
#pragma unroll
            for (int tn = 0; tn < 8; tn++) {
                int col = colbase + tn * 8;
                int cl = col & 127;
                float cm0 = cms[col], cm1 = cms[col + 1];
                float2 ga = *(const float2*)(gr0 + cl);
                float2 gb = *(const float2*)(gr1 + cl);
                float* cc = c[tm][tn];
                float v0 = fmaf(10.f, cc[0], cm0 + ga.x);
                float v1 = fmaf(10.f, cc[1], cm1 + ga.y);
                float v2 = fmaf(10.f, cc[2], cm0 + gb.x);
                float v3 = fmaf(10.f, cc[3], cm1 + gb.y);
                int s0 = tm * 2, s1 = tm * 2 + 1;
                if (v0 > best[s0]) { b2[s0] = best[s0]; best[s0] = v0; bm[s0] = col; }
                else if (v0 > b2[s0]) b2[s0] = v0;
                if (v1 > best[s0]) { b2[s0] = best[s0]; best[s0] = v1; bm[s0] = col + 1; }
                else if (v1 > b2[s0]) b2[s0] = v1;
                if (v2 > best[s1]) { b2[s1] = best[s1]; best[s1] = v2; bm[s1] = col; }
                else if (v2 > b2[s1]) b2[s1] = v2;
                if (v3 > best[s1]) { b2[s1] = best[s1]; best[s1] = v3; bm[s1] = col + 1; }
                else if (v3 > b2[s1]) b2[s1] = v3;
            }
        }
    }

    // quad reduce
#pragma unroll
    for (int s = 0; s < 4; s++) {
#pragma unroll
        for (int off = 1; off <= 2; off <<= 1) {
            float ov = __shfl_xor_sync(0xffffffffu, best[s], off);
            float o2 = __shfl_xor_sync(0xffffffffu, b2[s], off);
            int om = __shfl_xor_sync(0xffffffffu, bm[s], off);
            if (ov > best[s]) { b2[s] = fmaxf(best[s], o2); best[s] = ov; bm[s] = om; }
            else if (ov == best[s]) { b2[s] = best[s]; if (om < bm[s]) bm[s] = om; }
            else b2[s] = fmaxf(b2[s], fmaxf(ov, o2));
        }
    }
    __syncthreads();
    if (wc == 0 && (lane & 3) == 0) {
#pragma unroll
        for (int s = 0; s < 4; s++) {
            int lr = wr * 32 + (s >> 1) * 16 + ((s & 1) << 3) + (lane >> 2);
            redv[lr] = best[s]; redb[lr] = b2[s]; redi[lr] = bm[s];
        }
    }
    __syncthreads();
    if (wc == 1 && (lane & 3) == 0) {
#pragma unroll
        for (int s = 0; s < 4; s++) {
            int lr = wr * 32 + (s >> 1) * 16 + ((s & 1) << 3) + (lane >> 2);
            float ov = redv[lr], o2 = redb[lr]; int om = redi[lr];
            if (ov > best[s]) { b2[s] = fmaxf(best[s], o2); best[s] = ov; bm[s] = om; }
            else if (ov == best[s]) { b2[s] = best[s]; if (om < bm[s]) bm[s] = om; }
            else b2[s] = fmaxf(b2[s], fmaxf(ov, o2));
            int n = n0 + lr;
            g_idx[cbi][n] = bm[s];
            if (best[s] - b2[s] < 2e-2f) {
                int k = atomicAdd(&g_fixc, 1);
                g_fixn[k] = (cbi << 15) | n;
            }
        }
    }
}

// ---------- k_fix v2: exact fp32 rescore, float4 + 4-way ILP ----------
__global__ void k_fix(const float* __restrict__ cb, const float* __restrict__ gum) {
    __shared__ float4 xs4[32];
    __shared__ float rv[256];
    __shared__ int ri[256];
    int nfix = g_fixc;
    int tid = threadIdx.x;
    for (int it = blockIdx.x; it < nfix; it += gridDim.x) {
        int row = g_fixn[it];
        int cbi = row >> 15, n = row & 32767;
        if (tid < 32) xs4[tid] = *(const float4*)(&g_xf[cbi][n][tid * 4]);
        __syncthreads();
        const float4* e0 = (const float4*)(cb + (size_t)(cbi * M_ + tid) * D_);
        const float4* e1 = e0 + 256 * 32;
        const float4* e2 = e0 + 512 * 32;
        const float4* e3 = e0 + 768 * 32;
        float s0 = 0.f, s1 = 0.f, s2 = 0.f, s3 = 0.f;
#pragma unroll
        for (int d4 = 0; d4 < 32; d4++) {
            float4 x = xs4[d4];
            float4 a = e0[d4], b = e1[d4], cc = e2[d4], d = e3[d4];
            s0 += a.x * x.x + a.y * x.y + a.z * x.z + a.w * x.w;
            s1 += b.x * x.x + b.y * x.y + b.z * x.z + b.w * x.w;
            s2 += cc.x * x.x + cc.y * x.y + cc.z * x.z + cc.w * x.w;
            s3 += d.x * x.x + d.y * x.y + d.z * x.z + d.w * x.w;
        }
        const float* gr = gum + ((size_t)cbi * N_ + n) * (size_t)M_;
        float sc0 = 10.f * s0 + g_cm[cbi][tid]       + gr[tid];
        float sc1 = 10.f * s1 + g_cm[cbi][tid + 256] + gr[tid + 256];
        float sc2 = 10.f * s2 + g_cm[cbi][tid + 512] + gr[tid + 512];
        float sc3 = 10.f * s3 + g_cm[cbi][tid + 768] + gr[tid + 768];
        float best = sc0; int bmv = tid;
        if (sc1 > best) { best = sc1; bmv = tid + 256; }
        if (sc2 > best) { best = sc2; bmv = tid + 512; }
        if (sc3 > best) { best = sc3; bmv = tid + 768; }
        rv[tid] = best; ri[tid] = bmv;
        __syncthreads();
        for (int st = 128; st >= 1; st >>= 1) {
            if (tid < st) {
                if (rv[tid + st] > rv[tid] ||
                    (rv[tid + st] == rv[tid] && ri[tid + st] < ri[tid])) {
                    rv[tid] = rv[tid + st]; ri[tid] = ri[tid + st];
                }
            }
            __syncthreads();
        }
        if (tid == 0) g_idx[cbi][n] = ri[0];
        __syncthreads();
    }
}

// ---------- k_gather: vq_feat + inds outputs ----------
__global__ void k_gather(const float* __restrict__ cb, float* __restrict__ dout,
                         int write_vf, int write_inds) {
    int gt = blockIdx.x * 256 + threadIdx.x;
    int l4 = gt & 31;
    int t = (gt >> 5) & 4095;
    int b = gt >> 17;
    int l = l4 << 2;
    int ci = l >> 6;
    int cf = t & 1;
    int n = b * TC_ + (t >> 1);
    if (write_vf) {
        int idx = g_idx[ci][n];
        float4 v = *(const float4*)(cb + (size_t)(ci * M_ + idx) * D_ + (cf << 6) + (l & 63));
        *(float4*)(dout + OFF_VF + ((size_t)gt << 2)) = v;
    }
    if (write_inds && gt < 65536) {
        int ii = gt & 1, nn = gt >> 1;
        dout[OFF_IND + gt] = (float)g_idx[ii][nn];
    }
}

// ---------- k_out: out[b][f][t] = P[0][cf][idx0][f] + P[1][cf][idx1][f] ----------
__global__ void k_out(float* __restrict__ dout) {
    __shared__ float sm[32 * 256];
    __shared__ int idxs[64];
    int tid = threadIdx.x;
    int b = blockIdx.x >> 7;
    int t0 = (blockIdx.x & 127) << 5;
    if (tid < 32) {
        int n = b * TC_ + ((t0 + tid) >> 1);
        idxs[tid] = g_idx[0][n];
        idxs[32 + tid] = g_idx[1][n];
    }
    __syncthreads();
    float4* sm4 = (float4*)sm;
#pragma unroll
    for (int k = 0; k < 8; k++) {
        int u = tid + (k << 8);
        int tl = u >> 6, f4 = u & 63;
        int cf = tl & 1;
        const float4* p0 = (const float4*)&g_P[0][cf][idxs[tl]][f4 << 2];
        const float4* p1 = (const float4*)&g_P[1][cf][idxs[32 + tl]][f4 << 2];
        float4 a = *p0, bb = *p1;
        float4 v = make_float4(a.x + bb.x, a.y + bb.y, a.z + bb.z, a.w + bb.w);
        sm4[tl * 64 + (f4 ^ tl)] = v;
    }
    __syncthreads();
    int w = tid >> 5, lane = tid & 31;
#pragma unroll
    for (int j = 0; j < 32; j++) {
        int f = w * 32 + j;
        int cswz = ((f >> 2) ^ lane) & 63;
        float v = sm[lane * 256 + (cswz << 2) + (f & 3)];
        dout[(size_t)(b * F_ + f) * T_ + t0 + lane] = v;
    }
}

extern "C" void kernel_launch(void* const* d_in, const int* in_sizes, int n_in,
                              void* d_out, int out_size) {
    const float* in  = (const float*)d_in[0];
    const float* w1  = (const float*)d_in[1];
    const float* w2  = (const float*)d_in[2];
    const float* cb  = (const float*)d_in[3];
    const float* gum = (const float*)d_in[4];
    float* dout = (float*)d_out;

    int write_vf   = (out_size >= OFF_VF + B_ * T_ * L_) ? 1 : 0;
    int write_inds = (out_size >= OFF_IND + N_ * 2) ? 1 : 0;

    cudaFuncSetAttribute(k_dist_mma, cudaFuncAttributeMaxDynamicSharedMemorySize, DSM_TOT);

    k_prep2<<<dim3(32, 2, 2), 256>>>(cb, w2);
    k_prep<<<dim3(128, 2), 256>>>(cb);
    k_conv1<<<dim3(32, 16), 256>>>(in, w1);
    k_dist_mma<<<dim3(256, 2), 256, DSM_TOT>>>(gum);
    k_fix<<<256, 256>>>(cb, gum);
    k_gather<<<8192, 256>>>(cb, dout, write_vf, write_inds);
    k_out<<<2048, 256>>>(dout);
}

// round 12
// speedup vs baseline: 1.3416x; 1.2241x over previous
#include <cuda_runtime.h>
#include <cuda_bf16.h>
#include <cstdint>

#define B_   16
#define F_   256
#define T_   4096
#define L_   128
#define M_   1024
#define D_   128
#define TC_  2048
#define N_   32768

#define OFF_VF  16777216
#define OFF_IND 25165824

// device scratch
__device__ __align__(16) float         g_xf [2][N_][D_];
__device__ __align__(16) __nv_bfloat16 g_eh16[2][M_][D_];
__device__ __align__(16) __nv_bfloat16 g_el16[2][M_][D_];
__device__ __align__(16) float g_cm[2][M_];
__device__ __align__(16) int   g_idx[2][N_];
__device__ __align__(16) float g_P[2][2][M_][256];   // [i][cf][m][f]
__device__ int   g_fixc;
__device__ int   g_fixn[N_ * 2];

// ---- fp32x2 helpers ----
__device__ __forceinline__ unsigned long long pkdup(float x) {
    unsigned long long r; unsigned int xi = __float_as_uint(x);
    asm("mov.b64 %0, {%1, %2};" : "=l"(r) : "r"(xi), "r"(xi));
    return r;
}
__device__ __forceinline__ void ffma2(unsigned long long &acc, unsigned long long a,
                                      unsigned long long b) {
    asm("fma.rn.f32x2 %0, %1, %2, %0;" : "+l"(acc) : "l"(a), "l"(b));
}
__device__ __forceinline__ float2 upk(unsigned long long v) {
    unsigned int lo, hi;
    asm("mov.b64 {%0, %1}, %2;" : "=r"(lo), "=r"(hi) : "l"(v));
    float2 r; r.x = __uint_as_float(lo); r.y = __uint_as_float(hi);
    return r;
}

// ---- mma helpers ----
__device__ __forceinline__ uint32_t sm_u32(const void* p) {
    uint32_t a;
    asm("{ .reg .u64 t; cvta.to.shared.u64 t, %1; cvt.u32.u64 %0, t; }" : "=r"(a) : "l"(p));
    return a;
}
__device__ __forceinline__ void ldsm4(uint32_t& r0, uint32_t& r1, uint32_t& r2, uint32_t& r3,
                                      uint32_t a) {
    asm volatile("ldmatrix.sync.aligned.m8n8.x4.shared.b16 {%0,%1,%2,%3}, [%4];"
                 : "=r"(r0), "=r"(r1), "=r"(r2), "=r"(r3) : "r"(a));
}
__device__ __forceinline__ void mma16816(float* c, uint32_t a0, uint32_t a1, uint32_t a2,
                                         uint32_t a3, uint32_t b0, uint32_t b1) {
    asm volatile(
        "mma.sync.aligned.m16n8k16.row.col.f32.bf16.bf16.f32 "
        "{%0,%1,%2,%3},{%4,%5,%6,%7},{%8,%9},{%0,%1,%2,%3};"
        : "+f"(c[0]), "+f"(c[1]), "+f"(c[2]), "+f"(c[3])
        : "r"(a0), "r"(a1), "r"(a2), "r"(a3), "r"(b0), "r"(b1));
}
__device__ __forceinline__ uint32_t pk2(__nv_bfloat16 a, __nv_bfloat16 b) {
    unsigned short ra = *(unsigned short*)&a, rb = *(unsigned short*)&b;
    return (uint32_t)ra | ((uint32_t)rb << 16);
}

// ---------- k_prep: codebook bf16 hi/lo split + cm ----------
__global__ void k_prep(const float* __restrict__ cb) {
    if (blockIdx.x == 0 && blockIdx.y == 0 && threadIdx.x == 0) g_fixc = 0;
    int w = threadIdx.x >> 5, lane = threadIdx.x & 31;
    int i = blockIdx.y, m = blockIdx.x * 8 + w;
    const float* row = cb + (size_t)(i * M_ + m) * D_;
    float4 v = *(const float4*)(row + lane * 4);
    float s = v.x * v.x + v.y * v.y + v.z * v.z + v.w * v.w;
    float vv[4] = {v.x, v.y, v.z, v.w};
#pragma unroll
    for (int j = 0; j < 4; j++) {
        __nv_bfloat16 hb = __float2bfloat16(vv[j]);
        g_eh16[i][m][lane * 4 + j] = hb;
        g_el16[i][m][lane * 4 + j] = __float2bfloat16(vv[j] - __bfloat162float(hb));
    }
#pragma unroll
    for (int o = 16; o >= 1; o >>= 1) s += __shfl_xor_sync(0xffffffffu, s, o);
    if (lane == 0) g_cm[i][m] = -5.0f * s;
}

// ---------- k_prep2: P[i][cf][m][f] = sum_j e_i[m][cf*64+j] * w2[f][i*64+j] ----------
__global__ void k_prep2(const float* __restrict__ cb, const float* __restrict__ w2) {
    __shared__ float es[32][64];
    int tid = threadIdx.x;
    int m0 = blockIdx.x << 5, cf = blockIdx.y, i = blockIdx.z;
#pragma unroll
    for (int k = 0; k < 2; k++) {
        int u = tid + (k << 8);
        int m = u >> 4, d4 = u & 15;
        *(float4*)&es[m][d4 << 2] =
            *(const float4*)(cb + (size_t)(i * M_ + m0 + m) * D_ + cf * 64 + (d4 << 2));
    }
    __syncthreads();
    int f = tid;
    float4 wr[16];
    const float4* wp = (const float4*)(w2 + f * D_ + i * 64);
#pragma unroll
    for (int j = 0; j < 16; j++) wr[j] = wp[j];
#pragma unroll 4
    for (int m = 0; m < 32; m++) {
        float s = 0.f;
        const float4* ep = (const float4*)&es[m][0];
#pragma unroll
        for (int j = 0; j < 16; j++) {
            float4 e = ep[j], w = wr[j];
            s += e.x * w.x + e.y * w.y + e.z * w.z + e.w * w.w;
        }
        g_P[i][cf][m0 + m][f] = s;
    }
}

// ---------- k_conv1: conv1x1_1 -> g_xf only ----------
__global__ void __launch_bounds__(256, 2) k_conv1(const float* __restrict__ in,
                                                  const float* __restrict__ w1) {
    __shared__ float sm[2 * 32 * 136];
    float* Aw = sm;
    float* Bi = sm + 32 * 136;
    int tid = threadIdx.x, tx = tid & 15, ty = tid >> 4;
    int b = blockIdx.y, t0 = blockIdx.x << 7;

    unsigned long long acc[8][4];
#pragma unroll
    for (int a = 0; a < 8; a++)
#pragma unroll
        for (int q = 0; q < 4; q++) acc[a][q] = 0ULL;

    for (int kc = 0; kc < 8; kc++) {
        int f0 = kc << 5;
#pragma unroll
        for (int r = 0; r < 4; r++) {
            int lin = tid + (r << 8);
            int l = lin >> 3, fq = (lin & 7) << 2;
            float4 v = *(const float4*)(w1 + l * F_ + f0 + fq);
            Aw[(fq + 0) * 136 + l] = v.x; Aw[(fq + 1) * 136 + l] = v.y;
            Aw[(fq + 2) * 136 + l] = v.z; Aw[(fq + 3) * 136 + l] = v.w;
        }
#pragma unroll
        for (int r = 0; r < 4; r++) {
            int lin = tid + (r << 8);
            int f = lin >> 5, tq = (lin & 31) << 2;
            float4 v = *(const float4*)(in + (size_t)(b * F_ + f0 + f) * T_ + t0 + tq);
            *(float4*)(Bi + f * 136 + tq) = v;
        }
        __syncthreads();
#pragma unroll 8
        for (int f = 0; f < 32; f++) {
            float4 a0 = *(const float4*)(Aw + f * 136 + ty * 8);
            float4 a1 = *(const float4*)(Aw + f * 136 + ty * 8 + 4);
            const unsigned long long* bp = (const unsigned long long*)(Bi + f * 136 + tx * 8);
            unsigned long long b0 = bp[0], b1 = bp[1], b2 = bp[2], b3 = bp[3];
            unsigned long long ad[8] = {pkdup(a0.x), pkdup(a0.y), pkdup(a0.z), pkdup(a0.w),
                                        pkdup(a1.x), pkdup(a1.y), pkdup(a1.z), pkdup(a1.w)};
#pragma unroll
            for (int a = 0; a < 8; a++) {
                ffma2(acc[a][0], ad[a], b0);
                ffma2(acc[a][1], ad[a], b1);
                ffma2(acc[a][2], ad[a], b2);
                ffma2(acc[a][3], ad[a], b3);
            }
        }
        __syncthreads();
    }

    int nb = b * TC_ + (t0 >> 1);
    for (int h = 0; h < 2; h++) {
        if ((tx >> 3) == h) {
#pragma unroll
            for (int a = 0; a < 8; a++)
#pragma unroll
                for (int q = 0; q < 4; q++) {
                    float2 s = upk(acc[a][q]);
                    int tl = ((tx & 7) << 3) + (q << 1);
                    sm[tl * 129 + ty * 8 + a] = s.x;
                    sm[(tl + 1) * 129 + ty * 8 + a] = s.y;
                }
        }
        __syncthreads();
#pragma unroll
        for (int w = 0; w < 32; w++) {
            int e = (w << 8) + tid;
            int d = e & 127, cbb = (e >> 7) & 1, nn = e >> 8;
            float v = sm[(2 * nn + (d >> 6)) * 129 + (cbb << 6) + (d & 63)];
            g_xf[cbb][nb + h * 32 + nn][d] = v;
        }
        __syncthreads();
    }
}

// ---------- k_dist_mma (R7 core; X staged from g_xf with in-register split) ----------
// smem: Xh@0 (32K), Xl@32768, E@65536 (32K), cms@98304 (4K), red@102400
#define DSM_TOT 103936

__device__ __forceinline__ void do_pass(uint32_t sX, uint32_t sE, int lane, int wr, int wc,
                                        float c[2][8][4]) {
#pragma unroll
    for (int ks = 0; ks < 8; ks++) {
        uint32_t a[2][4];
#pragma unroll
        for (int tm = 0; tm < 2; tm++) {
            int rowA = wr * 32 + tm * 16 + (lane & 15);
            int koA = ks * 2 + (lane >> 4);
            ldsm4(a[tm][0], a[tm][1], a[tm][2], a[tm][3],
                  sX + rowA * 256 + ((koA ^ (rowA & 7)) << 4));
        }
#pragma unroll
        for (int pr = 0; pr < 4; pr++) {
            int nB = wc * 64 + pr * 16 + (lane & 7) + ((lane >> 4) << 3);
            int koB = ks * 2 + ((lane >> 3) & 1);
            uint32_t b0, b1, b2, b3;
            ldsm4(b0, b1, b2, b3, sE + nB * 256 + ((koB ^ (nB & 7)) << 4));
            mma16816(c[0][pr * 2],     a[0][0], a[0][1], a[0][2], a[0][3], b0, b1);
            mma16816(c[0][pr * 2 + 1], a[0][0], a[0][1], a[0][2], a[0][3], b2, b3);
            mma16816(c[1][pr * 2],     a[1][0], a[1][1], a[1][2], a[1][3], b0, b1);
            mma16816(c[1][pr * 2 + 1], a[1][0], a[1][1], a[1][2], a[1][3], b2, b3);
        }
    }
}

__global__ void __launch_bounds__(256, 1) k_dist_mma(const float* __restrict__ gum) {
    extern __shared__ char smem[];
    float* cms = (float*)(smem + 98304);
    float* redv = (float*)(smem + 102400);
    float* redb = redv + 128;
    int*   redi = (int*)(redb + 128);
    uint32_t sXh = sm_u32(smem), sXl = sXh + 32768, sE = sXh + 65536;

    int tid = threadIdx.x, lane = tid & 31, wid = tid >> 5;
    int wr = wid >> 1, wc = wid & 1;
    int cbi = blockIdx.y, n0 = blockIdx.x << 7;

    // stage X from g_xf: compute bf16 hi/lo split in-register (bitwise == old planes)
#pragma unroll
    for (int i = 0; i < 16; i++) {
        int lin = tid + (i << 8);            // 0..4095
        int row = lin >> 5, f4 = lin & 31;   // f4 = float4 index within row
        float4 v = *(const float4*)(&g_xf[cbi][n0 + row][f4 << 2]);
        __nv_bfloat16 h0 = __float2bfloat16(v.x), h1 = __float2bfloat16(v.y);
        __nv_bfloat16 h2 = __float2bfloat16(v.z), h3 = __float2bfloat16(v.w);
        __nv_bfloat16 l0 = __float2bfloat16(v.x - __bfloat162float(h0));
        __nv_bfloat16 l1 = __float2bfloat16(v.y - __bfloat162float(h1));
        __nv_bfloat16 l2 = __float2bfloat16(v.z - __bfloat162float(h2));
        __nv_bfloat16 l3 = __float2bfloat16(v.w - __bfloat162float(h3));
        uint32_t ko = f4 >> 1, half = f4 & 1;
        uint32_t off = row * 256 + ((ko ^ (row & 7)) << 4) + (half << 3);
        uint2 ph = make_uint2(pk2(h0, h1), pk2(h2, h3));
        uint2 pl = make_uint2(pk2(l0, l1), pk2(l2, l3));
        *(uint2*)(smem + off) = ph;
        *(uint2*)(smem + 32768 + off) = pl;
    }
    *(float4*)(&cms[tid * 4]) = *(const float4*)(&g_cm[cbi][tid * 4]);

    float best[4], b2[4]; int bm[4];
#pragma unroll
    for (int s = 0; s < 4; s++) { best[s] = -3.4e38f; b2[s] = -3.4e38f; bm[s] = 0; }

#pragma unroll 1
    for (int mc = 0; mc < 8; mc++) {
        float c[2][8][4];
#pragma unroll
        for (int tm = 0; tm < 2; tm++)
#pragma unroll
            for (int tn = 0; tn < 8; tn++)
#pragma unroll
                for (int q = 0; q < 4; q++) c[tm][tn][q] = 0.f;

        const __nv_bfloat16* ehp = &g_eh16[cbi][mc << 7][0];
        const __nv_bfloat16* elp = &g_el16[cbi][mc << 7][0];

        __syncthreads();
#pragma unroll
        for (int i = 0; i < 8; i++) {
            int lin = tid + (i << 8);
            int row = lin >> 4, ko = lin & 15;
            *(uint4*)(smem + 65536 + row * 256 + ((ko ^ (row & 7)) << 4)) =
                *(const uint4*)(ehp + row * 128 + ko * 8);
        }
        __syncthreads();
        do_pass(sXh, sE, lane, wr, wc, c);
        do_pass(sXl, sE, lane, wr, wc, c);
        __syncthreads();
#pragma unroll
        for (int i = 0; i < 8; i++) {
            int lin = tid + (i << 8);
            int row = lin >> 4, ko = lin & 15;
            *(uint4*)(smem + 65536 + row * 256 + ((ko ^ (row & 7)) << 4)) =
                *(const uint4*)(elp + row * 128 + ko * 8);
        }
        __syncthreads();
        do_pass(sXh, sE, lane, wr, wc, c);

        int colbase = (mc << 7) + wc * 64 + ((lane & 3) << 1);
#pragma unroll
        for (int tm = 0; tm < 2; tm++) {
            int r0 = n0 + wr * 32 + tm * 16 + (lane >> 2);
            const float* gr0 = gum + ((size_t)cbi * N_ + r0) * (size_t)M_;
            const float* gr1 = gr0 + (size_t)8 * M_;
#pragma unroll
            for (int tn = 0; tn < 8; tn++) {
                int col = colbase + tn * 8;
                float cm0 = cms[col], cm1 = cms[col + 1];
                float2 ga = *(const float2*)(gr0 + col);
                float2 gb = *(const float2*)(gr1 + col);
                float* cc = c[tm][tn];
                float v0 = fmaf(10.f, cc[0], cm0 + ga.x);
                float v1 = fmaf(10.f, cc[1], cm1 + ga.y);
                float v2 = fmaf(10.f, cc[2], cm0 + gb.x);
                float v3 = fmaf(10.f, cc[3], cm1 + gb.y);
                int s0 = tm * 2, s1 = tm * 2 + 1;
                if (v0 > best[s0]) { b2[s0] = best[s0]; best[s0] = v0; bm[s0] = col; }
                else if (v0 > b2[s0]) b2[s0] = v0;
                if (v1 > best[s0]) { b2[s0] = best[s0]; best[s0] = v1; bm[s0] = col + 1; }
                else if (v1 > b2[s0]) b2[s0] = v1;
                if (v2 > best[s1]) { b2[s1] = best[s1]; best[s1] = v2; bm[s1] = col; }
                else if (v2 > b2[s1]) b2[s1] = v2;
                if (v3 > best[s1]) { b2[s1] = best[s1]; best[s1] = v3; bm[s1] = col + 1; }
                else if (v3 > b2[s1]) b2[s1] = v3;
            }
        }
    }

#pragma unroll
    for (int s = 0; s < 4; s++) {
#pragma unroll
        for (int off = 1; off <= 2; off <<= 1) {
            float ov = __shfl_xor_sync(0xffffffffu, best[s], off);
            float o2 = __shfl_xor_sync(0xffffffffu, b2[s], off);
            int om = __shfl_xor_sync(0xffffffffu, bm[s], off);
            if (ov > best[s]) { b2[s] = fmaxf(best[s], o2); best[s] = ov; bm[s] = om; }
            else if (ov == best[s]) { b2[s] = best[s]; if (om < bm[s]) bm[s] = om; }
            else b2[s] = fmaxf(b2[s], fmaxf(ov, o2));
        }
    }
    __syncthreads();
    if (wc == 0 && (lane & 3) == 0) {
#pragma unroll
        for (int s = 0; s < 4; s++) {
            int lr = wr * 32 + (s >> 1) * 16 + ((s & 1) << 3) + (lane >> 2);
            redv[lr] = best[s]; redb[lr] = b2[s]; redi[lr] = bm[s];
        }
    }
    __syncthreads();
    if (wc == 1 && (lane & 3) == 0) {
#pragma unroll
        for (int s = 0; s < 4; s++) {
            int lr = wr * 32 + (s >> 1) * 16 + ((s & 1) << 3) + (lane >> 2);
            float ov = redv[lr], o2 = redb[lr]; int om = redi[lr];
            if (ov > best[s]) { b2[s] = fmaxf(best[s], o2); best[s] = ov; bm[s] = om; }
            else if (ov == best[s]) { b2[s] = best[s]; if (om < bm[s]) bm[s] = om; }
            else b2[s] = fmaxf(b2[s], fmaxf(ov, o2));
            int n = n0 + lr;
            g_idx[cbi][n] = bm[s];
            if (best[s] - b2[s] < 2e-2f) {
                int k = atomicAdd(&g_fixc, 1);
                g_fixn[k] = (cbi << 15) | n;
            }
        }
    }
}

// ---------- k_fix: exact fp32 rescore, float4 + 4-way ILP ----------
__global__ void k_fix(const float* __restrict__ cb, const float* __restrict__ gum) {
    __shared__ float4 xs4[32];
    __shared__ float rv[256];
    __shared__ int ri[256];
    int nfix = g_fixc;
    int tid = threadIdx.x;
    for (int it = blockIdx.x; it < nfix; it += gridDim.x) {
        int row = g_fixn[it];
        int cbi = row >> 15, n = row & 32767;
        if (tid < 32) xs4[tid] = *(const float4*)(&g_xf[cbi][n][tid * 4]);
        __syncthreads();
        const float4* e0 = (const float4*)(cb + (size_t)(cbi * M_ + tid) * D_);
        const float4* e1 = e0 + 256 * 32;
        const float4* e2 = e0 + 512 * 32;
        const float4* e3 = e0 + 768 * 32;
        float s0 = 0.f, s1 = 0.f, s2 = 0.f, s3 = 0.f;
#pragma unroll
        for (int d4 = 0; d4 < 32; d4++) {
            float4 x = xs4[d4];
            float4 a = e0[d4], b = e1[d4], cc = e2[d4], d = e3[d4];
            s0 += a.x * x.x + a.y * x.y + a.z * x.z + a.w * x.w;
            s1 += b.x * x.x + b.y * x.y + b.z * x.z + b.w * x.w;
            s2 += cc.x * x.x + cc.y * x.y + cc.z * x.z + cc.w * x.w;
            s3 += d.x * x.x + d.y * x.y + d.z * x.z + d.w * x.w;
        }
        const float* gr = gum + ((size_t)cbi * N_ + n) * (size_t)M_;
        float sc0 = 10.f * s0 + g_cm[cbi][tid]       + gr[tid];
        float sc1 = 10.f * s1 + g_cm[cbi][tid + 256] + gr[tid + 256];
        float sc2 = 10.f * s2 + g_cm[cbi][tid + 512] + gr[tid + 512];
        float sc3 = 10.f * s3 + g_cm[cbi][tid + 768] + gr[tid + 768];
        float best = sc0; int bmv = tid;
        if (sc1 > best) { best = sc1; bmv = tid + 256; }
        if (sc2 > best) { best = sc2; bmv = tid + 512; }
        if (sc3 > best) { best = sc3; bmv = tid + 768; }
        rv[tid] = best; ri[tid] = bmv;
        __syncthreads();
        for (int st = 128; st >= 1; st >>= 1) {
            if (tid < st) {
                if (rv[tid + st] > rv[tid] ||
                    (rv[tid + st] == rv[tid] && ri[tid + st] < ri[tid])) {
                    rv[tid] = rv[tid + st]; ri[tid] = ri[tid + st];
                }
            }
            __syncthreads();
        }
        if (tid == 0) g_idx[cbi][n] = ri[0];
        __syncthreads();
    }
}

// ---------- k_out: out + vq_feat + quant_inds (merged epilogue) ----------
__global__ void k_out(const float* __restrict__ cb, float* __restrict__ dout,
                      int write_vf, int write_inds) {
    __shared__ float sm[32 * 256];
    __shared__ int idxs[64];
    int tid = threadIdx.x;
    int b = blockIdx.x >> 7;
    int t0 = (blockIdx.x & 127) << 5;
    if (tid < 32) {
        int n = b * TC_ + ((t0 + tid) >> 1);
        idxs[tid] = g_idx[0][n];
        idxs[32 + tid] = g_idx[1][n];
    }
    __syncthreads();

    // quant_inds (float-cast), 16 n's per block
    if (write_inds && tid < 16) {
        int n = b * TC_ + (t0 >> 1) + tid;
        dout[OFF_IND + n * 2]     = (float)idxs[tid * 2];
        dout[OFF_IND + n * 2 + 1] = (float)idxs[32 + tid * 2];
    }
    // vq_feat: 32 t x 128 l = 1024 float4
    if (write_vf) {
#pragma unroll
        for (int k = 0; k < 4; k++) {
            int u = tid + (k << 8);
            int tl = u >> 5, l4 = u & 31;
            int l = l4 << 2, ci = l >> 6, cf = tl & 1;
            int idx = idxs[ci * 32 + tl];
            float4 v = *(const float4*)(cb + (size_t)(ci * M_ + idx) * D_
                                        + (cf << 6) + (l & 63));
            *(float4*)(dout + OFF_VF + (size_t)(b * T_ + t0 + tl) * L_ + l) = v;
        }
    }
    // out via P table
    float4* sm4 = (float4*)sm;
#pragma unroll
    for (int k = 0; k < 8; k++) {
        int u = tid + (k << 8);
        int tl = u >> 6, f4 = u & 63;
        int cf = tl & 1;
        const float4* p0 = (const float4*)&g_P[0][cf][idxs[tl]][f4 << 2];
        const float4* p1 = (const float4*)&g_P[1][cf][idxs[32 + tl]][f4 << 2];
        float4 a = *p0, bb = *p1;
        float4 v = make_float4(a.x + bb.x, a.y + bb.y, a.z + bb.z, a.w + bb.w);
        sm4[tl * 64 + (f4 ^ tl)] = v;
    }
    __syncthreads();
    int w = tid >> 5, lane = tid & 31;
#pragma unroll
    for (int j = 0; j < 32; j++) {
        int f = w * 32 + j;
        int cswz = ((f >> 2) ^ lane) & 63;
        float v = sm[lane * 256 + (cswz << 2) + (f & 3)];
        dout[(size_t)(b * F_ + f) * T_ + t0 + lane] = v;
    }
}

extern "C" void kernel_launch(void* const* d_in, const int* in_sizes, int n_in,
                              void* d_out, int out_size) {
    const float* in  = (const float*)d_in[0];
    const float* w1  = (const float*)d_in[1];
    const float* w2  = (const float*)d_in[2];
    const float* cb  = (const float*)d_in[3];
    const float* gum = (const float*)d_in[4];
    float* dout = (float*)d_out;

    int write_vf   = (out_size >= OFF_VF + B_ * T_ * L_) ? 1 : 0;
    int write_inds = (out_size >= OFF_IND + N_ * 2) ? 1 : 0;

    cudaFuncSetAttribute(k_dist_mma, cudaFuncAttributeMaxDynamicSharedMemorySize, DSM_TOT);

    k_prep2<<<dim3(32, 2, 2), 256>>>(cb, w2);
    k_prep<<<dim3(128, 2), 256>>>(cb);
    k_conv1<<<dim3(32, 16), 256>>>(in, w1);
    k_dist_mma<<<dim3(256, 2), 256, DSM_TOT>>>(gum);
    k_fix<<<256, 256>>>(cb, gum);
    k_out<<<2048, 256>>>(cb, dout, write_vf, write_inds);
}